// round 15
// baseline (speedup 1.0000x reference)
#include <cuda_runtime.h>
#include <stdint.h>

#define N        100800
#define NC       80
#define STRIDE   85
#define MAX_NMS  4096
#define MAX_DET  1000
#define CAP      16384
#define NB       256
#define SLOT     1024
#define KBASE    0x3ECCu
#define CONF_T   0.4f
#define IOU_T    0.45f
#define MAX_WH   7680.0f
#define ECAP     4096
#define CCAP     256
#define SBLK     296            // k_scores CTA count (2 waves of 148)

typedef unsigned long long u64;

// ---------------- scratch (static __device__, allocation-free) ----------------
__device__ unsigned int g_hist[NB];       // zeroed at final tail
__device__ unsigned int g_boff[NB];
__device__ unsigned int g_cutoff, g_total, g_bmax;
__device__ unsigned int g_ecnt = 0;       // zeroed at final tail
__device__ unsigned int g_done = 0;       // cedges last-block election
__device__ unsigned int g_sdone = 0;      // scores last-block election
__device__ unsigned int g_ccnt[NC];       // zeroed at final tail
__device__ unsigned int g_cls[NC * CCAP];
__device__ u64          g_bucket[NB * SLOT];   // 2MB direct-append segments
__device__ u64          g_cand[CAP];
__device__ float4       g_obox[MAX_NMS];
__device__ float        g_area[MAX_NMS];
__device__ float4       g_bbox[MAX_NMS];
__device__ float        g_score[MAX_NMS];
__device__ float        g_clsf[MAX_NMS];
__device__ unsigned int g_edge[ECAP];

// ---------------- K1: scores (grid-stride warps) + last-block suffix scan ----
__global__ void __launch_bounds__(1024)
k_scores(const float* __restrict__ pred) {
    __shared__ unsigned int s[NB];
    __shared__ int sb;
    __shared__ int s_last;
    const int tid  = threadIdx.x;
    const int lane = tid & 31;
    int gw = blockIdx.x * 32 + (tid >> 5);
    const int nwarps = SBLK * 32;

    for (int a = gw; a < N; a += nwarps) {
        const float* r = pred + (size_t)a * STRIDE;
        float v0 = r[lane];                          // x y w h obj cls[0..26]
        float obj = __shfl_sync(0xffffffffu, v0, 4);
        unsigned int key = 0u;
        if (obj > CONF_T) {                          // else conf <= obj <= 0.4
            float v1 = r[lane + 32];
            float v2 = (lane < 21) ? r[lane + 64] : 0.0f;
            float m = 0.0f;
            if (lane >= 5) m = __fmul_rn(v0, obj);
            m = fmaxf(m, __fmul_rn(v1, obj));
            if (lane < 21) m = fmaxf(m, __fmul_rn(v2, obj));
            unsigned int mu = __reduce_max_sync(0xffffffffu, __float_as_uint(m));
            if (__uint_as_float(mu) > CONF_T) key = mu;
        }
        if (lane == 0 && key) {
            unsigned int b = (key >> 16) - KBASE;
            if (b > 255u) b = 255u;
            unsigned int pos = atomicAdd(&g_hist[b], 1u);
            if (pos < SLOT)
                g_bucket[b * SLOT + pos] =
                    ((u64)key << 32) | (unsigned int)(~(unsigned int)a);
        }
    }

    // ---- last-block election -> suffix scan (fused former k_scan) ----
    __syncthreads();
    if (tid == 0) {
        __threadfence();
        s_last = (atomicAdd(&g_sdone, 1u) == SBLK - 1u);
    }
    __syncthreads();
    if (!s_last) return;

    unsigned int h = 0u;
    if (tid < NB) {
        h = g_hist[tid];
        if (h > SLOT) h = SLOT;             // clamp (overflow safety)
        g_hist[tid] = h;
        s[tid] = h;
    }
    if (tid == 0) sb = 0;
    __syncthreads();
    for (int off = 1; off < NB; off <<= 1) {
        unsigned int v = 0u;
        if (tid < NB && tid + off < NB) v = s[tid + off];
        __syncthreads();
        if (tid < NB) s[tid] += v;
        __syncthreads();
    }
    if (tid < NB) {
        g_boff[tid] = (tid < NB - 1) ? s[tid + 1] : 0u;
        if (s[tid] >= (unsigned)MAX_NMS &&
            (tid == NB - 1 || s[tid + 1] < (unsigned)MAX_NMS)) {
            g_cutoff = (unsigned)tid;
            g_total  = s[tid];
        }
        if (h) atomicMax(&sb, tid);
    }
    __syncthreads();
    if (tid == 0) {
        g_bmax = (unsigned)sb;
        if (s[0] < (unsigned)MAX_NMS) { g_cutoff = 0u; g_total = s[0]; }
    }
}

// ---------------- K2: per-bucket rank-by-count -> sorted g_cand ----------
__global__ void k_bsort() {
    __shared__ u64 sbuf[SLOT];          // 8KB
    const int tid = threadIdx.x;        // 256 threads
    unsigned int cutoff = g_cutoff, bmax = g_bmax;
    unsigned int limit = g_total;
    if (limit > (unsigned)MAX_NMS) limit = MAX_NMS;

    for (unsigned int b = cutoff + blockIdx.x; b <= bmax; b += gridDim.x) {
        unsigned int L = g_hist[b];                 // clamped <= SLOT
        if (L == 0) continue;
        unsigned int off = g_boff[b];
        if (off >= limit) continue;
        const u64* seg = g_bucket + (size_t)b * SLOT;
        if (L == 1) {
            if (tid == 0) g_cand[off] = seg[0];
            continue;
        }
        for (unsigned int j = tid; j < L; j += 256) sbuf[j] = seg[j];
        __syncthreads();
        u64 m0 = ((unsigned)tid        < L) ? sbuf[tid]       : ~0ULL;
        u64 m1 = ((unsigned)tid + 256u < L) ? sbuf[tid + 256] : ~0ULL;
        u64 m2 = ((unsigned)tid + 512u < L) ? sbuf[tid + 512] : ~0ULL;
        u64 m3 = ((unsigned)tid + 768u < L) ? sbuf[tid + 768] : ~0ULL;
        unsigned int c0 = 0, c1 = 0, c2 = 0, c3 = 0;
#pragma unroll 4
        for (unsigned int j = 0; j < L; j++) {
            u64 v = sbuf[j];
            c0 += (v > m0); c1 += (v > m1);
            c2 += (v > m2); c3 += (v > m3);
        }
        if ((unsigned)tid        < L) g_cand[off + c0] = m0;
        if ((unsigned)tid + 256u < L) g_cand[off + c1] = m1;
        if ((unsigned)tid + 512u < L) g_cand[off + c2] = m2;
        if ((unsigned)tid + 768u < L) g_cand[off + c3] = m3;
        __syncthreads();
    }
}

// ---------------- K3: warp-per-rank coalesced decode + class binning --------
__global__ void __launch_bounds__(1024)
k_decode(const float* __restrict__ pred) {
    int r    = blockIdx.x * 32 + (threadIdx.x >> 5);    // 128 blocks -> 4096 warps
    int lane = threadIdx.x & 31;
    unsigned int total = g_total;
    if (total > (unsigned)MAX_NMS) total = MAX_NMS;
    if ((unsigned)r >= total) return;       // rows >= total stay zero forever

    u64 key = g_cand[r];
    unsigned int kb  = (unsigned int)(key >> 32);
    unsigned int idx = ~(unsigned int)(key & 0xFFFFFFFFu);
    float score = __uint_as_float(kb);

    const float* row = pred + (size_t)idx * STRIDE;
    float v0 = row[lane];
    float v1 = row[lane + 32];
    float v2 = (lane < 21) ? row[lane + 64] : 0.0f;
    float obj = __shfl_sync(0xffffffffu, v0, 4);

    unsigned int cand = 0xFFu;
    if (lane >= 5 && __fmul_rn(v0, obj) == score)      cand = (unsigned)(lane - 5);
    else if (__fmul_rn(v1, obj) == score)              cand = (unsigned)(lane + 27);
    else if (lane < 21 && __fmul_rn(v2, obj) == score) cand = (unsigned)(lane + 59);
    unsigned int bestc = __reduce_min_sync(0xffffffffu, cand);

    float x = __shfl_sync(0xffffffffu, v0, 0);
    float y = __shfl_sync(0xffffffffu, v0, 1);
    float w = __shfl_sync(0xffffffffu, v0, 2);
    float h = __shfl_sync(0xffffffffu, v0, 3);

    if (lane == 0) {
        float hw = __fmul_rn(w, 0.5f), hh = __fmul_rn(h, 0.5f);
        float x1 = __fsub_rn(x, hw), y1 = __fsub_rn(y, hh);
        float x2 = __fadd_rn(x, hw), y2 = __fadd_rn(y, hh);
        float cf = (float)bestc;
        float off = __fmul_rn(cf, MAX_WH);
        float ox1 = __fadd_rn(x1, off), oy1 = __fadd_rn(y1, off);
        float ox2 = __fadd_rn(x2, off), oy2 = __fadd_rn(y2, off);
        float area = __fmul_rn(__fsub_rn(ox2, ox1), __fsub_rn(oy2, oy1));
        g_obox[r]  = make_float4(ox1, oy1, ox2, oy2);
        g_area[r]  = area;
        g_bbox[r]  = make_float4(x1, y1, x2, y2);
        g_score[r] = score;
        g_clsf[r]  = cf;
        unsigned int p = atomicAdd(&g_ccnt[bestc], 1u);
        if (p < CCAP) g_cls[bestc * CCAP + p] = (unsigned int)r;
    }
}

// ---------------- K4: per-class all-pairs edges + (last block) final --------
__global__ void k_cedges_final(float* __restrict__ out) {
    __shared__ union {
        struct { float4 sob[CCAP]; float sar[CCAP]; unsigned int sr[CCAP]; } a;
        struct { unsigned int se[4096]; unsigned int se2[4096]; } b;
    } U;
    __shared__ u64          keep[64];
    __shared__ unsigned int pref[64];
    __shared__ int          s_last;
    const int tid = threadIdx.x;            // 256 threads; grid = NC blocks

    // ---- per-class all-pairs IoU (symmetric in FP; edge set identical) ----
    {
        int c = blockIdx.x;
        unsigned int nc = g_ccnt[c];
        if (nc > CCAP) nc = CCAP;
        for (unsigned int i = tid; i < nc; i += 256) {
            unsigned int r = g_cls[c * CCAP + i];
            U.a.sr[i]  = r;
            U.a.sob[i] = g_obox[r];
            U.a.sar[i] = g_area[r];
        }
        __syncthreads();
        unsigned int np = nc * nc;
        for (unsigned int p = tid; p < np; p += 256) {
            unsigned int i = p / nc, j = p - i * nc;
            if (j <= i) continue;
            float4 A = U.a.sob[i], B = U.a.sob[j];
            float ltx = fmaxf(A.x, B.x), lty = fmaxf(A.y, B.y);
            float rbx = fminf(A.z, B.z), rby = fminf(A.w, B.w);
            float w = fmaxf(__fsub_rn(rbx, ltx), 0.0f);
            float h = fmaxf(__fsub_rn(rby, lty), 0.0f);
            float inter = __fmul_rn(w, h);
            if (inter > 0.0f) {
                float denom = __fadd_rn(
                    __fsub_rn(__fadd_rn(U.a.sar[i], U.a.sar[j]), inter), 1e-9f);
                float iou = __fdiv_rn(inter, denom);
                if (iou > IOU_T) {
                    unsigned int ri = U.a.sr[i], rj = U.a.sr[j];
                    unsigned int s = ri < rj ? ri : rj;
                    unsigned int d = ri < rj ? rj : ri;
                    unsigned int e = atomicAdd(&g_ecnt, 1u);
                    if (e < ECAP) g_edge[e] = (s << 12) | d;
                }
            }
        }
    }

    // ---- last-block election ----
    __syncthreads();
    if (tid == 0) {
        __threadfence();
        s_last = (atomicAdd(&g_done, 1u) == (unsigned)NC - 1u);
    }
    __syncthreads();
    if (!s_last) return;

    // ================= final block only =================
    unsigned int E = atomicAdd(&g_ecnt, 0u);
    if (E > ECAP) E = ECAP;
    unsigned int total = g_total;
    if (total > (unsigned)MAX_NMS) total = MAX_NMS;

    if (tid < 64) {
        unsigned int base = tid * 64u;
        u64 w;
        if (total >= base + 64u) w = ~0ULL;
        else if (total <= base)  w = 0ULL;
        else w = (1ULL << (total - base)) - 1ULL;
        keep[tid] = w;
    }
    __syncthreads();                         // union phase switch (a -> b)
    for (unsigned int i = tid; i < E; i += 256) U.b.se[i] = __ldcg(&g_edge[i]);
    __syncthreads();

    // rank-by-count ascending (edges distinct)
    for (unsigned int i = tid; i < E; i += 256) {
        unsigned int mine = U.b.se[i];
        unsigned int cnt = 0;
        for (unsigned int j = 0; j < E; j++) cnt += (U.b.se[j] < mine);
        U.b.se2[cnt] = mine;
    }
    __syncthreads();

    // sequential greedy: ascending src == exact fori_loop semantics
    if (tid == 0) {
        for (unsigned int e = 0; e < E; e++) {
            unsigned int kk = U.b.se2[e];
            unsigned int s = kk >> 12, d = kk & 4095u;
            if ((keep[s >> 6] >> (s & 63u)) & 1ULL)
                keep[d >> 6] &= ~(1ULL << (d & 63u));
        }
        unsigned int run = 0;
        for (int w = 0; w < 64; w++) { pref[w] = run; run += __popcll(keep[w]); }
    }
    __syncthreads();

    for (int j = tid; j < MAX_DET * 6; j += 256) out[j] = 0.0f;
    __syncthreads();
    for (int i = tid; i < MAX_NMS; i += 256) {
        u64 wv = keep[i >> 6];
        int b = i & 63;
        if ((wv >> b) & 1ULL) {
            unsigned int rank = pref[i >> 6] +
                (unsigned int)__popcll(wv & ((1ULL << b) - 1ULL));
            if (rank < (unsigned)MAX_DET) {
                float4 bb = g_bbox[i];
                float* o = out + (size_t)rank * 6;
                o[0] = bb.x; o[1] = bb.y; o[2] = bb.z; o[3] = bb.w;
                o[4] = g_score[i]; o[5] = g_clsf[i];
            }
        }
    }

    // ---- reset state for next graph replay (deterministic) ----
    if (tid < NB) g_hist[tid] = 0u;
    if (tid < NC) g_ccnt[tid] = 0u;
    if (tid == 0) {
        g_ecnt = 0u;
        atomicExch(&g_sdone, 0u);
        atomicExch(&g_done, 0u);
    }
}

// ---------------- launch: 4 nodes ----------------
extern "C" void kernel_launch(void* const* d_in, const int* in_sizes, int n_in,
                              void* d_out, int out_size) {
    const float* pred = (const float*)d_in[0];
    float* out = (float*)d_out;

    k_scores      <<<SBLK, 1024>>>(pred);
    k_bsort       <<<64, 256>>>();
    k_decode      <<<MAX_NMS / 32, 1024>>>(pred);
    k_cedges_final<<<NC, 256>>>(out);
}